// round 4
// baseline (speedup 1.0000x reference)
#include <cuda_runtime.h>
#include <math.h>

#define LSEQ   32768
#define BATCH  16
#define NSEQ   32            // BATCH * 2 directions
#define CL     512           // chunk length (scan order)
#define NCH    (LSEQ/CL)     // 64 chunks per sequence
#define TILE   128           // tokens per phase-A tile == blockDim of k1
#define NTILES (CL/TILE)     // 4
#define EPSV   1e-5f

// ---------------- scratch (device globals; no cudaMalloc allowed) ----------
__device__ float4 g_yp[NSEQ*LSEQ];        // gated partial y (zero-init scan)
__device__ float4 g_gz[NSEQ*LSEQ];        // silu(z) gate
__device__ float4 g_Dp[NSEQ*LSEQ];        // inclusive dt-prefix within chunk
__device__ float4 g_Cm[NSEQ*LSEQ*4];      // C (16 floats / token)
__device__ float  g_S [NSEQ*NCH*4];       // chunk total dt sum
__device__ float  g_Q [NSEQ*NCH*64];      // chunk-final h (zero-init scan)
__device__ float  g_hp[NSEQ*NCH*64];      // true h at chunk start

__device__ __forceinline__ float siluf(float x) {
    return __fdividef(x, 1.f + __expf(-x));
}
__device__ __forceinline__ float softplusf(float x) {
    return fmaxf(x, 0.f) + log1pf(__expf(-fabsf(x)));
}

// ============================ K1: per-chunk preprocess + zero-init scan =====
__global__ __launch_bounds__(TILE) void k1(
    const float* __restrict__ hs,
    const float* __restrict__ nw,  const float* __restrict__ ipw,
    const float* __restrict__ cwf, const float* __restrict__ cbf,
    const float* __restrict__ xpf, const float* __restrict__ dtwf,
    const float* __restrict__ dtbf,const float* __restrict__ Alf,
    const float* __restrict__ Dwf,
    const float* __restrict__ cwb, const float* __restrict__ cbb,
    const float* __restrict__ xpb, const float* __restrict__ dtwb,
    const float* __restrict__ dtbb,const float* __restrict__ Alb,
    const float* __restrict__ Dwb)
{
    __shared__ float sA[64];          // A = -exp(A_log)
    __shared__ float sxp[132];        // x_proj_w (33,4)
    __shared__ float sip[16];         // in_proj_w (8,2)
    __shared__ float scw[16], scb[4], sdtw[4], sdtb[4], snw[2], sDw[4];
    __shared__ float sx[4][CL+4];     // conv input x, scan order, 3-halo left
    __shared__ float rec[TILE][49];   // dt(4) dtu(4) B(16) C(16) g(4) udg(4)
    __shared__ float sY[TILE][4];
    __shared__ float sDb[TILE][4];

    const int tid = threadIdx.x;
    const int ch  = blockIdx.x;
    const int s   = blockIdx.y;
    const int dir = s & 1;
    const int b   = s >> 1;

    const float* cw  = dir ? cwb  : cwf;
    const float* cb  = dir ? cbb  : cbf;
    const float* xp  = dir ? xpb  : xpf;
    const float* dtw = dir ? dtwb : dtwf;
    const float* dtb = dir ? dtbb : dtbf;
    const float* Al  = dir ? Alb  : Alf;
    const float* Dw  = dir ? Dwb  : Dwf;

    if (tid < 64) sA[tid] = -__expf(Al[tid]);
    else if (tid < 80) sip[tid-64] = ipw[tid-64];
    for (int i = tid; i < 132; i += TILE) sxp[i] = xp[i];
    if (tid < 16) scw[tid] = cw[tid];
    if (tid < 4) { scb[tid]=cb[tid]; sdtw[tid]=dtw[tid]; sdtb[tid]=dtb[tid]; sDw[tid]=Dw[tid]; }
    if (tid < 2) snw[tid] = nw[tid];
    __syncthreads();

    const int cs = ch * CL;
    const float* hb0 = hs + (size_t)b*2*LSEQ;
    const float* hb1 = hb0 + LSEQ;

    // stage conv input x for scan positions [cs-3, cs+CL)
    for (int m = tid; m < CL+3; m += TILE) {
        int p = cs - 3 + m;
        float x0=0.f,x1=0.f,x2=0.f,x3=0.f;
        if (p >= 0) {
            int l = dir ? (LSEQ-1-p) : p;
            float h0 = hb0[l], h1 = hb1[l];
            float r = rsqrtf(0.5f*(h0*h0 + h1*h1) + EPSV);
            float n0 = h0*r*snw[0], n1 = h1*r*snw[1];
            x0 = sip[0]*n0 + sip[1]*n1;
            x1 = sip[2]*n0 + sip[3]*n1;
            x2 = sip[4]*n0 + sip[5]*n1;
            x3 = sip[6]*n0 + sip[7]*n1;
        }
        sx[0][m]=x0; sx[1][m]=x1; sx[2][m]=x2; sx[3][m]=x3;
    }
    __syncthreads();

    float hk   = 0.f;   // per-state h (tid < 64)
    float Dacc = 0.f;   // per-d dt prefix (tid < 4)
    const int kd = tid >> 4, kn = tid & 15;

    for (int tt = 0; tt < NTILES; tt++) {
        const int p = cs + tt*TILE + tid;     // this thread's token (scan order)
        // ---------------- phase A: per-token pipeline ----------------
        {
            const int m = tt*TILE + tid;      // = p - cs
            float u[4], dt[4], Bv[16], Cv[16];
            #pragma unroll
            for (int d = 0; d < 4; d++) {
                float xc = scb[d];
                #pragma unroll
                for (int j = 0; j < 4; j++) xc = fmaf(scw[d*4+j], sx[d][m+j], xc);
                u[d] = siluf(xc);
            }
            float dtraw = 0.f;
            #pragma unroll
            for (int d = 0; d < 4; d++) dtraw = fmaf(u[d], sxp[d], dtraw);
            #pragma unroll
            for (int n = 0; n < 16; n++) {
                float bv = 0.f, cv = 0.f;
                #pragma unroll
                for (int d = 0; d < 4; d++) {
                    bv = fmaf(u[d], sxp[(1+n)*4+d],  bv);
                    cv = fmaf(u[d], sxp[(17+n)*4+d], cv);
                }
                Bv[n]=bv; Cv[n]=cv;
            }
            #pragma unroll
            for (int d = 0; d < 4; d++) dt[d] = softplusf(fmaf(dtraw, sdtw[d], sdtb[d]));
            // gate from z
            int l = dir ? (LSEQ-1-p) : p;
            float h0 = hb0[l], h1 = hb1[l];
            float r = rsqrtf(0.5f*(h0*h0 + h1*h1) + EPSV);
            float n0 = h0*r*snw[0], n1 = h1*r*snw[1];
            float g[4], udg[4];
            #pragma unroll
            for (int d = 0; d < 4; d++) {
                float z = sip[(4+d)*2]*n0 + sip[(4+d)*2+1]*n1;
                g[d]   = siluf(z);
                udg[d] = u[d]*sDw[d]*g[d];
            }
            #pragma unroll
            for (int d = 0; d < 4; d++) {
                rec[tid][d]    = dt[d];
                rec[tid][4+d]  = dt[d]*u[d];
                rec[tid][40+d] = g[d];
                rec[tid][44+d] = udg[d];
            }
            #pragma unroll
            for (int n = 0; n < 16; n++) { rec[tid][8+n]=Bv[n]; rec[tid][24+n]=Cv[n]; }

            size_t idx = (size_t)s*LSEQ + p;
            g_gz[idx] = make_float4(g[0],g[1],g[2],g[3]);
            g_Cm[idx*4+0] = make_float4(Cv[0], Cv[1], Cv[2], Cv[3]);
            g_Cm[idx*4+1] = make_float4(Cv[4], Cv[5], Cv[6], Cv[7]);
            g_Cm[idx*4+2] = make_float4(Cv[8], Cv[9], Cv[10],Cv[11]);
            g_Cm[idx*4+3] = make_float4(Cv[12],Cv[13],Cv[14],Cv[15]);
        }
        __syncthreads();
        // ---------------- phase B: serial zero-init scan over tile ----------
        if (tid < 64) {
            const float Ak = sA[tid];
            #pragma unroll 4
            for (int tok = 0; tok < TILE; tok++) {
                float dtv = rec[tok][kd];
                float a   = __expf(Ak * dtv);
                float bb  = rec[tok][4+kd] * rec[tok][8+kn];
                hk = fmaf(a, hk, bb);
                float v = hk * rec[tok][24+kn];
                v += __shfl_xor_sync(0xffffffffu, v, 8);
                v += __shfl_xor_sync(0xffffffffu, v, 4);
                v += __shfl_xor_sync(0xffffffffu, v, 2);
                v += __shfl_xor_sync(0xffffffffu, v, 1);
                if (kn == 0) sY[tok][kd] = v;
                if (tid < 4) { Dacc += rec[tok][tid]; sDb[tok][tid] = Dacc; }
            }
        }
        __syncthreads();
        // ---------------- write gated partial y + dt prefix -----------------
        {
            size_t idx = (size_t)s*LSEQ + p;
            float y0 = fmaf(sY[tid][0], rec[tid][40], rec[tid][44]);
            float y1 = fmaf(sY[tid][1], rec[tid][41], rec[tid][45]);
            float y2 = fmaf(sY[tid][2], rec[tid][42], rec[tid][46]);
            float y3 = fmaf(sY[tid][3], rec[tid][43], rec[tid][47]);
            g_yp[idx] = make_float4(y0,y1,y2,y3);
            g_Dp[idx] = make_float4(sDb[tid][0],sDb[tid][1],sDb[tid][2],sDb[tid][3]);
        }
        __syncthreads();
    }
    if (tid < 64) g_Q[((size_t)s*NCH + ch)*64 + tid] = hk;
    if (tid < 4)  g_S[((size_t)s*NCH + ch)*4  + tid] = Dacc;
}

// ============================ K2: cross-chunk prefix ========================
__global__ __launch_bounds__(64) void k2(const float* __restrict__ Alf,
                                         const float* __restrict__ Alb)
{
    const int s = blockIdx.x;
    const int k = threadIdx.x;
    const int d = k >> 4;
    const float* Al = (s & 1) ? Alb : Alf;
    const float Ak = -__expf(Al[k]);
    float h = 0.f;
    for (int c = 0; c < NCH; c++) {
        size_t base = (size_t)s*NCH + c;
        g_hp[base*64 + k] = h;
        float a = __expf(Ak * g_S[base*4 + d]);
        h = fmaf(a, h, g_Q[base*64 + k]);
    }
}

// ============================ K3: correction + epilogue =====================
__global__ __launch_bounds__(256) void k3(
    const float* __restrict__ hs,
    const float* __restrict__ Alf, const float* __restrict__ Alb,
    const float* __restrict__ opw, const float* __restrict__ nfw,
    float* __restrict__ out)
{
    __shared__ float sAA[2][64];
    __shared__ float sop[8];
    __shared__ float snf[2];
    const int tid = threadIdx.x;
    if (tid < 64)       sAA[0][tid]     = -__expf(Alf[tid]);
    else if (tid < 128) sAA[1][tid-64]  = -__expf(Alb[tid-64]);
    else if (tid < 136) sop[tid-128]    = opw[tid-128];
    else if (tid < 138) snf[tid-136]    = nfw[tid-136];
    __syncthreads();

    const int gi = blockIdx.x*256 + tid;
    const int b  = gi >> 15;          // / LSEQ
    const int l  = gi & (LSEQ-1);

    float y[4] = {0.f,0.f,0.f,0.f};
    #pragma unroll
    for (int dir = 0; dir < 2; dir++) {
        int s = b*2 + dir;
        int t = dir ? (LSEQ-1-l) : l;
        int ch = t >> 9;              // / CL
        size_t idx = (size_t)s*LSEQ + t;
        float4 yp = g_yp[idx];
        float4 gz = g_gz[idx];
        float4 Dp = g_Dp[idx];
        float4 c0 = g_Cm[idx*4+0], c1 = g_Cm[idx*4+1];
        float4 c2 = g_Cm[idx*4+2], c3 = g_Cm[idx*4+3];
        float Cv[16] = {c0.x,c0.y,c0.z,c0.w, c1.x,c1.y,c1.z,c1.w,
                        c2.x,c2.y,c2.z,c2.w, c3.x,c3.y,c3.z,c3.w};
        float Dv[4]  = {Dp.x,Dp.y,Dp.z,Dp.w};
        float gv[4]  = {gz.x,gz.y,gz.z,gz.w};
        float ypv[4] = {yp.x,yp.y,yp.z,yp.w};
        const float* hp = &g_hp[((size_t)s*NCH + ch)*64];
        const float* A  = sAA[dir];
        #pragma unroll
        for (int d = 0; d < 4; d++) {
            float corr = 0.f;
            #pragma unroll
            for (int n = 0; n < 16; n++) {
                float E = __expf(A[d*16+n] * Dv[d]);
                corr = fmaf(Cv[n]*E, __ldg(&hp[d*16+n]), corr);
            }
            y[d] += fmaf(corr, gv[d], ypv[d]);
        }
    }
    float h0 = hs[(size_t)b*2*LSEQ + l];
    float h1 = hs[(size_t)b*2*LSEQ + LSEQ + l];
    float o0 = h0, o1 = h1;
    #pragma unroll
    for (int d = 0; d < 4; d++) {
        o0 = fmaf(sop[d],   y[d], o0);
        o1 = fmaf(sop[4+d], y[d], o1);
    }
    float r = rsqrtf(0.5f*(o0*o0 + o1*o1) + EPSV);
    out[(size_t)b*2*LSEQ + l]        = o0*r*snf[0];
    out[(size_t)b*2*LSEQ + LSEQ + l] = o1*r*snf[1];
}

// ============================ launch ========================================
extern "C" void kernel_launch(void* const* d_in, const int* in_sizes, int n_in,
                              void* d_out, int out_size)
{
    const float* hs   = (const float*)d_in[0];
    const float* nw   = (const float*)d_in[1];
    const float* ipw  = (const float*)d_in[2];
    const float* cwf  = (const float*)d_in[3];
    const float* cbf  = (const float*)d_in[4];
    const float* xpf  = (const float*)d_in[5];
    const float* dtwf = (const float*)d_in[6];
    const float* dtbf = (const float*)d_in[7];
    const float* Alf  = (const float*)d_in[8];
    const float* Dwf  = (const float*)d_in[9];
    const float* cwb  = (const float*)d_in[10];
    const float* cbb  = (const float*)d_in[11];
    const float* xpb  = (const float*)d_in[12];
    const float* dtwb = (const float*)d_in[13];
    const float* dtbb = (const float*)d_in[14];
    const float* Alb  = (const float*)d_in[15];
    const float* Dwb  = (const float*)d_in[16];
    const float* opw  = (const float*)d_in[17];
    const float* nfw  = (const float*)d_in[18];
    float* out = (float*)d_out;

    k1<<<dim3(NCH, NSEQ), TILE>>>(hs, nw, ipw,
                                  cwf, cbf, xpf, dtwf, dtbf, Alf, Dwf,
                                  cwb, cbb, xpb, dtwb, dtbb, Alb, Dwb);
    k2<<<NSEQ, 64>>>(Alf, Alb);
    k3<<<(BATCH*LSEQ)/256, 256>>>(hs, Alf, Alb, opw, nfw, out);
}

// round 5
// speedup vs baseline: 2.2458x; 2.2458x over previous
#include <cuda_runtime.h>
#include <math.h>

#define LSEQ   32768
#define BATCH  16
#define NSEQ   32            // BATCH * 2 directions
#define CL     512           // chunk length (scan order)
#define NCH    (LSEQ/CL)     // 64 chunks per sequence
#define ST     64            // sub-tile tokens (per sequence half)
#define NST    (CL/ST)       // 8
#define EPSV   1e-5f

// ---------------- scratch (device globals; no cudaMalloc allowed) ----------
__device__ float4 g_yp[NSEQ*LSEQ];        // gated partial y (zero-init scan)
__device__ float4 g_gz[NSEQ*LSEQ];        // silu(z) gate
__device__ float4 g_Dp[NSEQ*LSEQ];        // inclusive dt-prefix within chunk
__device__ float4 g_Cm[NSEQ*LSEQ*4];      // C (16 floats / token)
__device__ float  g_S [NSEQ*NCH*4];       // chunk total dt sum
__device__ float  g_Q [NSEQ*NCH*64];      // chunk-final h (zero-init scan)
__device__ float  g_hp[NSEQ*NCH*64];      // true h at chunk start

__device__ __forceinline__ float siluf(float x) {
    return __fdividef(x, 1.f + __expf(-x));
}
__device__ __forceinline__ float softplusf(float x) {
    return fmaxf(x, 0.f) + log1pf(__expf(-fabsf(x)));
}

// ============================ K1 ============================================
// One block = one chunk of BOTH directions of one batch element.
// half = tid>>6 selects direction; 64 threads per half.
// Per sub-tile of 64 tokens:
//   phase A (token-parallel): rmsnorm -> in_proj -> conv -> silu -> x_proj
//            -> dt/B/C/gate; dt,dt*u,B to smem; C,g,u*D*g stay in registers.
//   phase B (state-parallel, serial over 64 tokens): h = exp(A*dt)*h + dtu*B,
//            stored to smem. No shuffles, no reductions in the loop.
//   phase C (token-parallel): y = (C . h)*g + u*D*g, global stores.
__global__ __launch_bounds__(128, 4) void k1(
    const float* __restrict__ hs,
    const float* __restrict__ nw,  const float* __restrict__ ipw,
    const float* __restrict__ cwf, const float* __restrict__ cbf,
    const float* __restrict__ xpf, const float* __restrict__ dtwf,
    const float* __restrict__ dtbf,const float* __restrict__ Alf,
    const float* __restrict__ Dwf,
    const float* __restrict__ cwb, const float* __restrict__ cbb,
    const float* __restrict__ xpb, const float* __restrict__ dtwb,
    const float* __restrict__ dtbb,const float* __restrict__ Alb,
    const float* __restrict__ Dwb)
{
    __shared__ float sA[2][64];
    __shared__ float sxp[2][132];
    __shared__ float sip[16];
    __shared__ float scw[2][16], scb[2][4], sdtw[2][4], sdtb[2][4], sDw[2][4];
    __shared__ float snw[2];
    __shared__ float sx[2][4][ST+4];     // conv input, per sub-tile, 3-halo
    __shared__ float rec[2][ST][25];     // dt(4) dtu(4) B(16)
    __shared__ float sh[2][ST][65];      // h per token per state (padded)
    __shared__ float sDp[2][ST][5];      // dt inclusive prefix (padded)

    const int tid  = threadIdx.x;
    const int half = tid >> 6;           // 0: fwd dir, 1: bwd dir
    const int lt   = tid & 63;           // local token / state id
    const int ch   = blockIdx.x;
    const int b    = blockIdx.y;
    const int s    = b*2 + half;
    const int dir  = half;

    // weight load (both directions)
    if (tid < 64)       { sA[0][tid] = -__expf(Alf[tid]); }
    else                { sA[1][lt]  = -__expf(Alb[lt]); }
    for (int i = tid; i < 132; i += 128) { sxp[0][i] = xpf[i]; sxp[1][i] = xpb[i]; }
    if (tid < 16) { scw[0][tid] = cwf[tid]; scw[1][tid] = cwb[tid]; sip[tid] = ipw[tid]; }
    if (tid < 4)  { scb[0][tid]=cbf[tid];  scb[1][tid]=cbb[tid];
                    sdtw[0][tid]=dtwf[tid];sdtw[1][tid]=dtwb[tid];
                    sdtb[0][tid]=dtbf[tid];sdtb[1][tid]=dtbb[tid];
                    sDw[0][tid]=Dwf[tid];  sDw[1][tid]=Dwb[tid]; }
    if (tid < 2)  snw[tid] = nw[tid];
    __syncthreads();

    const int cs = ch * CL;
    const float* hb0 = hs + (size_t)b*2*LSEQ;
    const float* hb1 = hb0 + LSEQ;

    const int   kd = lt >> 4, kn = lt & 15;
    const float Ak = sA[half][lt];
    float hk   = 0.f;                    // per-state h
    float Dacc = 0.f;                    // dt prefix (kn==0 threads)

    for (int tt = 0; tt < NST; tt++) {
        const int ts = cs + tt*ST;
        const int p  = ts + lt;          // this thread's token (scan order)

        // ---- stage conv inputs for [ts-3, ts+ST) ----
        for (int m = lt; m < ST+3; m += 64) {
            int pp = ts - 3 + m;
            float x0=0.f,x1=0.f,x2=0.f,x3=0.f;
            if (pp >= 0) {
                int l = dir ? (LSEQ-1-pp) : pp;
                float h0 = hb0[l], h1 = hb1[l];
                float r = rsqrtf(0.5f*(h0*h0 + h1*h1) + EPSV);
                float n0 = h0*r*snw[0], n1 = h1*r*snw[1];
                x0 = sip[0]*n0 + sip[1]*n1;
                x1 = sip[2]*n0 + sip[3]*n1;
                x2 = sip[4]*n0 + sip[5]*n1;
                x3 = sip[6]*n0 + sip[7]*n1;
            }
            sx[half][0][m]=x0; sx[half][1][m]=x1; sx[half][2][m]=x2; sx[half][3][m]=x3;
        }
        __syncthreads();

        // ---- phase A ----
        float Cv[16], gg[4], udg[4];
        {
            float u[4], dt[4], Bv[16];
            #pragma unroll
            for (int d = 0; d < 4; d++) {
                float xc = scb[half][d];
                #pragma unroll
                for (int j = 0; j < 4; j++) xc = fmaf(scw[half][d*4+j], sx[half][d][lt+j], xc);
                u[d] = siluf(xc);
            }
            float dtraw = 0.f;
            #pragma unroll
            for (int d = 0; d < 4; d++) dtraw = fmaf(u[d], sxp[half][d], dtraw);
            #pragma unroll
            for (int n = 0; n < 16; n++) {
                float bv = 0.f, cv = 0.f;
                #pragma unroll
                for (int d = 0; d < 4; d++) {
                    bv = fmaf(u[d], sxp[half][(1+n)*4+d],  bv);
                    cv = fmaf(u[d], sxp[half][(17+n)*4+d], cv);
                }
                Bv[n]=bv; Cv[n]=cv;
            }
            #pragma unroll
            for (int d = 0; d < 4; d++)
                dt[d] = softplusf(fmaf(dtraw, sdtw[half][d], sdtb[half][d]));
            // gate from z
            int l = dir ? (LSEQ-1-p) : p;
            float h0 = hb0[l], h1 = hb1[l];
            float r = rsqrtf(0.5f*(h0*h0 + h1*h1) + EPSV);
            float n0 = h0*r*snw[0], n1 = h1*r*snw[1];
            #pragma unroll
            for (int d = 0; d < 4; d++) {
                float z = sip[(4+d)*2]*n0 + sip[(4+d)*2+1]*n1;
                gg[d]  = siluf(z);
                udg[d] = u[d]*sDw[half][d]*gg[d];
            }
            #pragma unroll
            for (int d = 0; d < 4; d++) {
                rec[half][lt][d]   = dt[d];
                rec[half][lt][4+d] = dt[d]*u[d];
            }
            #pragma unroll
            for (int n = 0; n < 16; n++) rec[half][lt][8+n] = Bv[n];

            size_t idx = (size_t)s*LSEQ + p;
            g_gz[idx] = make_float4(gg[0],gg[1],gg[2],gg[3]);
            g_Cm[idx*4+0] = make_float4(Cv[0], Cv[1], Cv[2], Cv[3]);
            g_Cm[idx*4+1] = make_float4(Cv[4], Cv[5], Cv[6], Cv[7]);
            g_Cm[idx*4+2] = make_float4(Cv[8], Cv[9], Cv[10],Cv[11]);
            g_Cm[idx*4+3] = make_float4(Cv[12],Cv[13],Cv[14],Cv[15]);
        }
        __syncthreads();

        // ---- phase B: serial zero-init scan, all 128 threads (64 states x 2 seqs)
        #pragma unroll 4
        for (int tok = 0; tok < ST; tok++) {
            float dtv = rec[half][tok][kd];
            float a   = __expf(Ak * dtv);
            float bb  = rec[half][tok][4+kd] * rec[half][tok][8+kn];
            hk = fmaf(a, hk, bb);
            sh[half][tok][lt] = hk;
            if (kn == 0) { Dacc += dtv; sDp[half][tok][kd] = Dacc; }
        }
        __syncthreads();

        // ---- phase C: token-parallel reduction + stores ----
        {
            size_t idx = (size_t)s*LSEQ + p;
            float y[4];
            #pragma unroll
            for (int d = 0; d < 4; d++) {
                float acc = 0.f;
                #pragma unroll
                for (int n = 0; n < 16; n++)
                    acc = fmaf(Cv[n], sh[half][lt][d*16+n], acc);
                y[d] = fmaf(acc, gg[d], udg[d]);
            }
            g_yp[idx] = make_float4(y[0],y[1],y[2],y[3]);
            g_Dp[idx] = make_float4(sDp[half][lt][0], sDp[half][lt][1],
                                    sDp[half][lt][2], sDp[half][lt][3]);
        }
        __syncthreads();
    }
    g_Q[((size_t)s*NCH + ch)*64 + lt] = hk;
    if (kn == 0) g_S[((size_t)s*NCH + ch)*4 + kd] = Dacc;
}

// ============================ K2: cross-chunk prefix ========================
__global__ __launch_bounds__(64) void k2(const float* __restrict__ Alf,
                                         const float* __restrict__ Alb)
{
    const int s = blockIdx.x;
    const int k = threadIdx.x;
    const int d = k >> 4;
    const float* Al = (s & 1) ? Alb : Alf;
    const float Ak = -__expf(Al[k]);
    float h = 0.f;
    for (int c = 0; c < NCH; c++) {
        size_t base = (size_t)s*NCH + c;
        g_hp[base*64 + k] = h;
        float a = __expf(Ak * g_S[base*4 + d]);
        h = fmaf(a, h, g_Q[base*64 + k]);
    }
}

// ============================ K3: correction + epilogue =====================
__global__ __launch_bounds__(256) void k3(
    const float* __restrict__ hs,
    const float* __restrict__ Alf, const float* __restrict__ Alb,
    const float* __restrict__ opw, const float* __restrict__ nfw,
    float* __restrict__ out)
{
    __shared__ float sAA[2][64];
    __shared__ float sop[8];
    __shared__ float snf[2];
    const int tid = threadIdx.x;
    if (tid < 64)       sAA[0][tid]     = -__expf(Alf[tid]);
    else if (tid < 128) sAA[1][tid-64]  = -__expf(Alb[tid-64]);
    else if (tid < 136) sop[tid-128]    = opw[tid-128];
    else if (tid < 138) snf[tid-136]    = nfw[tid-136];
    __syncthreads();

    const int gi = blockIdx.x*256 + tid;
    const int b  = gi >> 15;          // / LSEQ
    const int l  = gi & (LSEQ-1);

    float y[4] = {0.f,0.f,0.f,0.f};
    #pragma unroll
    for (int dir = 0; dir < 2; dir++) {
        int s = b*2 + dir;
        int t = dir ? (LSEQ-1-l) : l;
        int ch = t >> 9;              // / CL
        size_t idx = (size_t)s*LSEQ + t;
        float4 yp = g_yp[idx];
        float4 gz = g_gz[idx];
        float4 Dp = g_Dp[idx];
        float4 c0 = g_Cm[idx*4+0], c1 = g_Cm[idx*4+1];
        float4 c2 = g_Cm[idx*4+2], c3 = g_Cm[idx*4+3];
        float Cv[16] = {c0.x,c0.y,c0.z,c0.w, c1.x,c1.y,c1.z,c1.w,
                        c2.x,c2.y,c2.z,c2.w, c3.x,c3.y,c3.z,c3.w};
        float Dv[4]  = {Dp.x,Dp.y,Dp.z,Dp.w};
        float gv[4]  = {gz.x,gz.y,gz.z,gz.w};
        float ypv[4] = {yp.x,yp.y,yp.z,yp.w};
        const float* hp = &g_hp[((size_t)s*NCH + ch)*64];
        const float* A  = sAA[dir];
        #pragma unroll
        for (int d = 0; d < 4; d++) {
            float corr = 0.f;
            #pragma unroll
            for (int n = 0; n < 16; n++) {
                float E = __expf(A[d*16+n] * Dv[d]);
                corr = fmaf(Cv[n]*E, __ldg(&hp[d*16+n]), corr);
            }
            y[d] += fmaf(corr, gv[d], ypv[d]);
        }
    }
    float h0 = hs[(size_t)b*2*LSEQ + l];
    float h1 = hs[(size_t)b*2*LSEQ + LSEQ + l];
    float o0 = h0, o1 = h1;
    #pragma unroll
    for (int d = 0; d < 4; d++) {
        o0 = fmaf(sop[d],   y[d], o0);
        o1 = fmaf(sop[4+d], y[d], o1);
    }
    float r = rsqrtf(0.5f*(o0*o0 + o1*o1) + EPSV);
    out[(size_t)b*2*LSEQ + l]        = o0*r*snf[0];
    out[(size_t)b*2*LSEQ + LSEQ + l] = o1*r*snf[1];
}

// ============================ launch ========================================
extern "C" void kernel_launch(void* const* d_in, const int* in_sizes, int n_in,
                              void* d_out, int out_size)
{
    const float* hs   = (const float*)d_in[0];
    const float* nw   = (const float*)d_in[1];
    const float* ipw  = (const float*)d_in[2];
    const float* cwf  = (const float*)d_in[3];
    const float* cbf  = (const float*)d_in[4];
    const float* xpf  = (const float*)d_in[5];
    const float* dtwf = (const float*)d_in[6];
    const float* dtbf = (const float*)d_in[7];
    const float* Alf  = (const float*)d_in[8];
    const float* Dwf  = (const float*)d_in[9];
    const float* cwb  = (const float*)d_in[10];
    const float* cbb  = (const float*)d_in[11];
    const float* xpb  = (const float*)d_in[12];
    const float* dtwb = (const float*)d_in[13];
    const float* dtbb = (const float*)d_in[14];
    const float* Alb  = (const float*)d_in[15];
    const float* Dwb  = (const float*)d_in[16];
    const float* opw  = (const float*)d_in[17];
    const float* nfw  = (const float*)d_in[18];
    float* out = (float*)d_out;

    k1<<<dim3(NCH, BATCH), 128>>>(hs, nw, ipw,
                                  cwf, cbf, xpf, dtwf, dtbf, Alf, Dwf,
                                  cwb, cbb, xpb, dtwb, dtbb, Alb, Dwb);
    k2<<<NSEQ, 64>>>(Alf, Alb);
    k3<<<(BATCH*LSEQ)/256, 256>>>(hs, Alf, Alb, opw, nfw, out);
}